// round 15
// baseline (speedup 1.0000x reference)
#include <cuda_runtime.h>
#include <cuda_bf16.h>

typedef unsigned int u32;
typedef unsigned long long u64;

#define BB   8
#define CC   128
#define NN   2000
#define NKS  32000
#define TIL  500          // s-tiles of 64 per batch
#define TSI  64

// conv0 smem (bytes): W 256B-pitch tiles, x 128B-pitch tiles
#define C_WH   0
#define C_WL   32768
#define C_XH   65536
#define C_XL   81920
#define C_BUF  0                   // fp32 [64][132] = 33792, overlaps dead W
#define C_S4   98304               // fp32 [4][128] = 2048
#define C_SMEM (98304 + 2048)

// k_attn smem: A half-tiles (128o x 64k, 128B pitch), hn (64s x 128c, 256B pitch)
#define A_WAH  0
#define A_WAL  16384
#define A_WBH  32768
#define A_WBL  49152
#define A_HH   65536
#define A_HL   81920
#define A_SMEM 98304

// Scratch (device globals: allocation-free rule)
__device__ __align__(16) float g_h[(size_t)BB * NKS * CC];   // h as [b][s][c]
__device__ float g_psum[BB * TIL * CC];
__device__ float g_psq [BB * TIL * CC];
__device__ __align__(16) float g_scale[BB * CC];
__device__ __align__(16) float g_shift[BB * CC];

// ---------------------------------------------------------------------------
// helpers
// ---------------------------------------------------------------------------
__device__ __forceinline__ u32 smem_u32(const void* p) {
    u32 a;
    asm("{ .reg .u64 t; cvta.to.shared.u64 t, %1; cvt.u32.u64 %0, t; }" : "=r"(a) : "l"(p));
    return a;
}

// a -> low half, b -> high half; hi/lo bf16 split of the fp32 pair
__device__ __forceinline__ void split2(float a, float b, u32& hi, u32& lo) {
    u32 h;
    asm("cvt.rn.bf16x2.f32 %0, %1, %2;" : "=r"(h) : "f"(b), "f"(a));
    float fa = __uint_as_float(h << 16);
    float fb = __uint_as_float(h & 0xffff0000u);
    float la = a - fa, lb = b - fb;
    asm("cvt.rn.bf16x2.f32 %0, %1, %2;" : "=r"(lo) : "f"(lb), "f"(la));
    hi = h;
}

__device__ __forceinline__ void ldsm4(u32 r[4], u32 addr) {
    asm volatile("ldmatrix.sync.aligned.m8n8.x4.shared.b16 {%0,%1,%2,%3}, [%4];"
        : "=r"(r[0]), "=r"(r[1]), "=r"(r[2]), "=r"(r[3]) : "r"(addr));
}
__device__ __forceinline__ void ldsm4t(u32 r[4], u32 addr) {
    asm volatile("ldmatrix.sync.aligned.m8n8.x4.trans.shared.b16 {%0,%1,%2,%3}, [%4];"
        : "=r"(r[0]), "=r"(r[1]), "=r"(r[2]), "=r"(r[3]) : "r"(addr));
}
__device__ __forceinline__ void mma16816(float d[4], const u32 a[4], const u32 b[2]) {
    asm volatile("mma.sync.aligned.m16n8k16.row.col.f32.bf16.bf16.f32 "
        "{%0,%1,%2,%3}, {%4,%5,%6,%7}, {%8,%9}, {%0,%1,%2,%3};"
        : "+f"(d[0]), "+f"(d[1]), "+f"(d[2]), "+f"(d[3])
        : "r"(a[0]), "r"(a[1]), "r"(a[2]), "r"(a[3]), "r"(b[0]), "r"(b[1]));
}

// Stage full 128x128 fp32 weight -> hi/lo bf16 tiles, 256B pitch, swizzled. 256 thr.
__device__ __forceinline__ void stage_w_full(char* smc, int offHi, int offLo,
                                             const float* __restrict__ w, int t) {
#pragma unroll
    for (int i = 0; i < 16; i++) {
        int f = i * 256 + t;
        int o = f >> 5, c0 = (f & 31) << 2;
        float4 v = reinterpret_cast<const float4*>(w)[f];
        u32 h0, l0, h1, l1;
        split2(v.x, v.y, h0, l0);
        split2(v.z, v.w, h1, l1);
        u32 ad = (u32)(o * 256) + (u32)((c0 * 2) ^ ((o & 7) << 4));
        *reinterpret_cast<u64*>(smc + offHi + ad) = ((u64)h1 << 32) | h0;
        *reinterpret_cast<u64*>(smc + offLo + ad) = ((u64)l1 << 32) | l0;
    }
}

// Stage one k-half (64 cols) of a 128x128 fp32 weight -> hi/lo tiles, 128B pitch. 256 thr.
__device__ __forceinline__ void stage_w_half(char* smc, int offHi, int offLo,
                                             const float* __restrict__ w, int kh, int t) {
#pragma unroll
    for (int i = 0; i < 8; i++) {
        int f = i * 256 + t;
        int o = f >> 4, c0 = (f & 15) << 2;
        float4 v = *reinterpret_cast<const float4*>(w + o * 128 + kh * 64 + c0);
        u32 h0, l0, h1, l1;
        split2(v.x, v.y, h0, l0);
        split2(v.z, v.w, h1, l1);
        u32 ad = (u32)(o * 128) + (u32)((c0 * 2) ^ ((o & 7) << 4));
        *reinterpret_cast<u64*>(smc + offHi + ad) = ((u64)h1 << 32) | h0;
        *reinterpret_cast<u64*>(smc + offLo + ad) = ((u64)l1 << 32) | l0;
    }
}

// ---------------------------------------------------------------------------
// Kernel 1: h = W0 @ x + b0 via mma.sync (bf16-split), h stored [b][s][c];
// per-tile partial sum/sumsq. grid (500, 8), 256 threads, 2 CTAs/SM.
// ---------------------------------------------------------------------------
__global__ __launch_bounds__(256, 2) void k_conv0(const float* __restrict__ x,
                                                  const float* __restrict__ w0,
                                                  const float* __restrict__ b0) {
    extern __shared__ char smc[];
    u32 sm32 = smem_u32(smc);
    int t = threadIdx.x, wid = t >> 5, L = t & 31;
    int b = blockIdx.y, tile = blockIdx.x;
    int s0 = tile * TSI;

    // A = W0 [o][c] hi/lo (256B pitch)
    stage_w_full(smc, C_WH, C_WL, w0, t);

    // B = x tile [c][s0..s0+64), 128B pitch, pairs along s
    {
        int c = t >> 1, q = t & 1;
        const float4* src = reinterpret_cast<const float4*>(
            x + ((size_t)b * CC + c) * NKS + s0) + q * 8;
        u32 rowbase = (u32)(c * 128);
        u32 xm = (u32)((c & 7) << 4);
#pragma unroll
        for (int i = 0; i < 8; i++) {
            float4 v = src[i];
            u32 h0, l0, h1, l1;
            split2(v.x, v.y, h0, l0);
            split2(v.z, v.w, h1, l1);
            u32 ad = rowbase + (((u32)(q * 64 + i * 8)) ^ xm);
            *reinterpret_cast<u64*>(smc + C_XH + ad) = ((u64)h1 << 32) | h0;
            *reinterpret_cast<u64*>(smc + C_XL + ad) = ((u64)l1 << 32) | l0;
        }
    }
    __syncthreads();

    int obase = (wid & 3) * 32, sbase = (wid >> 2) * 32;
    int m = L >> 3;
    int rA_off = (m & 1) * 8 + (L & 7);   // A row offset within 16
    int kbA_off = (m >> 1) * 16;          // A k-byte offset
    int krB_off = (m & 1) * 8 + (L & 7);  // B (trans) k-row offset within 16
    int cbB = sbase * 2 + (m >> 1) * 16;  // B col-byte base

    float d[2][4][4];
#pragma unroll
    for (int mf = 0; mf < 2; mf++)
#pragma unroll
        for (int nf = 0; nf < 4; nf++)
#pragma unroll
            for (int j = 0; j < 4; j++) d[mf][nf][j] = 0.f;

#pragma unroll
    for (int ks = 0; ks < 8; ks++) {
        u32 bh[4][2], bl[4][2];
        int krow = ks * 16 + krB_off;
        u32 rowb = (u32)(krow * 128);
        u32 xm = (u32)((krow & 7) << 4);
#pragma unroll
        for (int np = 0; np < 2; np++) {
            u32 ad = rowb + (((u32)(cbB + np * 32)) ^ xm);
            u32 r[4];
            ldsm4t(r, sm32 + C_XH + ad);
            bh[np * 2][0] = r[0]; bh[np * 2][1] = r[1];
            bh[np * 2 + 1][0] = r[2]; bh[np * 2 + 1][1] = r[3];
            ldsm4t(r, sm32 + C_XL + ad);
            bl[np * 2][0] = r[0]; bl[np * 2][1] = r[1];
            bl[np * 2 + 1][0] = r[2]; bl[np * 2 + 1][1] = r[3];
        }
        u32 ah[2][4], al[2][4];
#pragma unroll
        for (int mf = 0; mf < 2; mf++) {
            int row = obase + mf * 16 + rA_off;
            u32 ad = (u32)(row * 256) + (u32)((ks * 32 + kbA_off) ^ ((row & 7) << 4));
            ldsm4(ah[mf], sm32 + C_WH + ad);
            ldsm4(al[mf], sm32 + C_WL + ad);
        }
#pragma unroll
        for (int mf = 0; mf < 2; mf++)
#pragma unroll
            for (int nf = 0; nf < 4; nf++) {
                mma16816(d[mf][nf], ah[mf], bh[nf]);
                mma16816(d[mf][nf], ah[mf], bl[nf]);
                mma16816(d[mf][nf], al[mf], bh[nf]);
            }
    }
    __syncthreads();   // W/X dead; buf overlaps them

    // stage D[o][s] -> buf[s][o] (pitch 132)
    float* buf = reinterpret_cast<float*>(smc + C_BUF);
#pragma unroll
    for (int mf = 0; mf < 2; mf++)
#pragma unroll
        for (int nf = 0; nf < 4; nf++)
#pragma unroll
            for (int j = 0; j < 4; j++) {
                int srow = sbase + nf * 8 + (L & 3) * 2 + (j & 1);
                int o = obase + mf * 16 + (L >> 2) + (j >> 1) * 8;
                buf[srow * 132 + o] = d[mf][nf][j];
            }
    __syncthreads();

    // read buf rows, add bias, write g_h[b][s][c] coalesced + stats partials
    {
        float* s4 = reinterpret_cast<float*>(smc + C_S4);
        int c = t & 127, sq = t >> 7;          // sq in {0,1}
        float bias = b0[c];
        float sacc = 0.f, qacc = 0.f;
#pragma unroll 4
        for (int i = 0; i < 32; i++) {
            int srow = sq * 32 + i;
            float v = buf[srow * 132 + c] + bias;
            g_h[((size_t)b * NKS + s0 + srow) * CC + c] = v;
            sacc += v; qacc += v * v;
        }
        s4[sq * 128 + c] = sacc;
        s4[256 + sq * 128 + c] = qacc;
        __syncthreads();
        if (t < 128) {
            float s = s4[t] + s4[128 + t];
            float q = s4[256 + t] + s4[384 + t];
            int pi = (b * TIL + tile) * CC + t;
            g_psum[pi] = s;
            g_psq[pi] = q;
        }
    }
}

// ---------------------------------------------------------------------------
// Kernel 2: collapse IN + BN -> per-(b,c) affine. After IN, per-(b,c) mean==0
// and var==v/(v+eps_in); BN batch mean==0, BN var==mean_b[v/(v+eps_in)].
// ---------------------------------------------------------------------------
__global__ void k_stats(const float* __restrict__ bn_g, const float* __restrict__ bn_b) {
    __shared__ float rmat[BB][CC];
    __shared__ float bsc[CC];
    int t = threadIdx.x;
    int b = t >> 7, c = t & 127;

    float s = 0.f, q = 0.f;
    for (int i = 0; i < TIL; i++) {
        int idx = (b * TIL + i) * CC + c;
        s += g_psum[idx];
        q += g_psq[idx];
    }
    const float inv_n = 1.0f / (float)NKS;
    float mu  = s * inv_n;
    float var = fmaxf(q * inv_n - mu * mu, 0.f);
    rmat[b][c] = var / (var + 1e-3f);
    __syncthreads();
    if (t < CC) {
        float ss = 0.f;
#pragma unroll
        for (int i = 0; i < BB; i++) ss += rmat[i][t];
        bsc[t] = rsqrtf(ss * (1.0f / BB) + 1e-5f);
    }
    __syncthreads();
    float scale = rsqrtf(var + 1e-3f) * bsc[c] * bn_g[c];
    g_scale[b * CC + c] = scale;
    g_shift[b * CC + c] = bn_b[c] - mu * scale;
}

// ---------------------------------------------------------------------------
// Kernel 3: hn = relu(affine(h)); q,k,v GEMMs via mma.sync (bf16-split, k-halved
// weight staging so q&k share B loads); softmax over K=16 via quad shfl; residual.
// grid (500, 8), 256 threads, 2 CTAs/SM.
// ---------------------------------------------------------------------------
__global__ __launch_bounds__(256, 2) void k_attn(
    const float* __restrict__ x_row,
    const float* __restrict__ wq, const float* __restrict__ bq,
    const float* __restrict__ wk, const float* __restrict__ bk,
    const float* __restrict__ wv, const float* __restrict__ bv,
    const float* __restrict__ gamma1, float* __restrict__ out) {
    extern __shared__ char smc[];
    u32 sm32 = smem_u32(smc);
    int t = threadIdx.x, wid = t >> 5, L = t & 31;
    int b = blockIdx.y, tile = blockIdx.x;
    int s0 = tile * TSI;

    // hn tile [s][c] (64 rows x 256B): read g_h[b][s][c], affine+relu, split
    {
        int srow = t >> 2, cb = (t & 3) * 32;
        const float4* hp  = reinterpret_cast<const float4*>(
            g_h + ((size_t)b * NKS + s0 + srow) * CC + cb);
        const float4* scp = reinterpret_cast<const float4*>(g_scale + b * CC + cb);
        const float4* shp = reinterpret_cast<const float4*>(g_shift + b * CC + cb);
        u32 rowb = (u32)(srow * 256);
        u32 xm = (u32)((srow & 7) << 4);
#pragma unroll
        for (int i = 0; i < 8; i++) {
            float4 v  = hp[i];
            float4 sc = scp[i];
            float4 sh = shp[i];
            v.x = fmaxf(fmaf(v.x, sc.x, sh.x), 0.f);
            v.y = fmaxf(fmaf(v.y, sc.y, sh.y), 0.f);
            v.z = fmaxf(fmaf(v.z, sc.z, sh.z), 0.f);
            v.w = fmaxf(fmaf(v.w, sc.w, sh.w), 0.f);
            u32 h0, l0, h1, l1;
            split2(v.x, v.y, h0, l0);
            split2(v.z, v.w, h1, l1);
            u32 ad = rowb + (((u32)(cb * 2 + i * 8)) ^ xm);
            *reinterpret_cast<u64*>(smc + A_HH + ad) = ((u64)h1 << 32) | h0;
            *reinterpret_cast<u64*>(smc + A_HL + ad) = ((u64)l1 << 32) | l0;
        }
    }
    stage_w_half(smc, A_WAH, A_WAL, wq, 0, t);
    stage_w_half(smc, A_WBH, A_WBL, wk, 0, t);
    __syncthreads();

    int obase = (wid & 3) * 32, sbase = (wid >> 2) * 32;
    int m = L >> 3;
    int rA_off = (m & 1) * 8 + (L & 7);
    int kbA_off = (m >> 1) * 16;
    int nrB_off = ((m >> 1) & 1) * 8 + (L & 7);  // B non-trans: n-row offset
    int kbB_off = (m & 1) * 16;

    float dq[2][4][4], dk[2][4][4];
#pragma unroll
    for (int mf = 0; mf < 2; mf++)
#pragma unroll
        for (int nf = 0; nf < 4; nf++)
#pragma unroll
            for (int j = 0; j < 4; j++) { dq[mf][nf][j] = 0.f; dk[mf][nf][j] = 0.f; }

    // phase 1: q and k GEMMs, k-halved A staging, shared B loads
#pragma unroll
    for (int kh = 0; kh < 2; kh++) {
        if (kh) {
            __syncthreads();
            stage_w_half(smc, A_WAH, A_WAL, wq, 1, t);
            stage_w_half(smc, A_WBH, A_WBL, wk, 1, t);
            __syncthreads();
        }
#pragma unroll
        for (int ksl = 0; ksl < 4; ksl++) {
            int ksg = kh * 4 + ksl;
            u32 bh[4][2], bl[4][2];
#pragma unroll
            for (int np = 0; np < 2; np++) {
                int nrow = sbase + np * 16 + nrB_off;
                u32 ad = (u32)(nrow * 256) + (u32)((ksg * 32 + kbB_off) ^ ((nrow & 7) << 4));
                u32 r[4];
                ldsm4(r, sm32 + A_HH + ad);
                bh[np * 2][0] = r[0]; bh[np * 2][1] = r[1];
                bh[np * 2 + 1][0] = r[2]; bh[np * 2 + 1][1] = r[3];
                ldsm4(r, sm32 + A_HL + ad);
                bl[np * 2][0] = r[0]; bl[np * 2][1] = r[1];
                bl[np * 2 + 1][0] = r[2]; bl[np * 2 + 1][1] = r[3];
            }
            u32 ah[2][4], al[2][4];
#pragma unroll
            for (int mf = 0; mf < 2; mf++) {
                int row = obase + mf * 16 + rA_off;
                u32 ad = (u32)(row * 128) + (u32)((ksl * 32 + kbA_off) ^ ((row & 7) << 4));
                ldsm4(ah[mf], sm32 + A_WAH + ad);
                ldsm4(al[mf], sm32 + A_WAL + ad);
            }
#pragma unroll
            for (int mf = 0; mf < 2; mf++)
#pragma unroll
                for (int nf = 0; nf < 4; nf++) {
                    mma16816(dq[mf][nf], ah[mf], bh[nf]);
                    mma16816(dq[mf][nf], ah[mf], bl[nf]);
                    mma16816(dq[mf][nf], al[mf], bh[nf]);
                }
#pragma unroll
            for (int mf = 0; mf < 2; mf++) {
                int row = obase + mf * 16 + rA_off;
                u32 ad = (u32)(row * 128) + (u32)((ksl * 32 + kbA_off) ^ ((row & 7) << 4));
                ldsm4(ah[mf], sm32 + A_WBH + ad);
                ldsm4(al[mf], sm32 + A_WBL + ad);
            }
#pragma unroll
            for (int mf = 0; mf < 2; mf++)
#pragma unroll
                for (int nf = 0; nf < 4; nf++) {
                    mma16816(dk[mf][nf], ah[mf], bh[nf]);
                    mma16816(dk[mf][nf], ah[mf], bl[nf]);
                    mma16816(dk[mf][nf], al[mf], bh[nf]);
                }
        }
    }

    // p = (q+bq)*(k+bk) in-place into dq
    float bqv[2][2], bkv[2][2], bvv[2][2];
#pragma unroll
    for (int mf = 0; mf < 2; mf++)
#pragma unroll
        for (int hf = 0; hf < 2; hf++) {
            int o = obase + mf * 16 + (L >> 2) + hf * 8;
            bqv[mf][hf] = bq[o]; bkv[mf][hf] = bk[o]; bvv[mf][hf] = bv[o];
        }
#pragma unroll
    for (int mf = 0; mf < 2; mf++)
#pragma unroll
        for (int nf = 0; nf < 4; nf++)
#pragma unroll
            for (int j = 0; j < 4; j++) {
                int hf = j >> 1;
                dq[mf][nf][j] = (dq[mf][nf][j] + bqv[mf][hf]) * (dk[mf][nf][j] + bkv[mf][hf]);
            }

    // phase 2: v GEMM (dk reused as accumulator)
#pragma unroll
    for (int mf = 0; mf < 2; mf++)
#pragma unroll
        for (int nf = 0; nf < 4; nf++)
#pragma unroll
            for (int j = 0; j < 4; j++) dk[mf][nf][j] = 0.f;

#pragma unroll
    for (int kh = 0; kh < 2; kh++) {
        __syncthreads();
        stage_w_half(smc, A_WAH, A_WAL, wv, kh, t);
        __syncthreads();
#pragma unroll
        for (int ksl = 0; ksl < 4; ksl++) {
            int ksg = kh * 4 + ksl;
            u32 bh[4][2], bl[4][2];
#pragma unroll
            for (int np = 0; np < 2; np++) {
                int nrow = sbase + np * 16 + nrB_off;
                u32 ad = (u32)(nrow * 256) + (u32)((ksg * 32 + kbB_off) ^ ((nrow & 7) << 4));
                u32 r[4];
                ldsm4(r, sm32 + A_HH + ad);
                bh[np * 2][0] = r[0]; bh[np * 2][1] = r[1];
                bh[np * 2 + 1][0] = r[2]; bh[np * 2 + 1][1] = r[3];
                ldsm4(r, sm32 + A_HL + ad);
                bl[np * 2][0] = r[0]; bl[np * 2][1] = r[1];
                bl[np * 2 + 1][0] = r[2]; bl[np * 2 + 1][1] = r[3];
            }
            u32 ah[2][4], al[2][4];
#pragma unroll
            for (int mf = 0; mf < 2; mf++) {
                int row = obase + mf * 16 + rA_off;
                u32 ad = (u32)(row * 128) + (u32)((ksl * 32 + kbA_off) ^ ((row & 7) << 4));
                ldsm4(ah[mf], sm32 + A_WAH + ad);
                ldsm4(al[mf], sm32 + A_WAL + ad);
            }
#pragma unroll
            for (int mf = 0; mf < 2; mf++)
#pragma unroll
                for (int nf = 0; nf < 4; nf++) {
                    mma16816(dk[mf][nf], ah[mf], bh[nf]);
                    mma16816(dk[mf][nf], ah[mf], bl[nf]);
                    mma16816(dk[mf][nf], al[mf], bh[nf]);
                }
        }
    }

    // epilogue: softmax over 16-s groups (quad shfl) + weighted V + residual
    float gm = gamma1[0];
#pragma unroll
    for (int mf = 0; mf < 2; mf++)
#pragma unroll
        for (int hf = 0; hf < 2; hf++)
#pragma unroll
            for (int g = 0; g < 2; g++) {
                float p0 = dq[mf][2 * g][hf * 2],     p1 = dq[mf][2 * g][hf * 2 + 1];
                float p2 = dq[mf][2 * g + 1][hf * 2], p3 = dq[mf][2 * g + 1][hf * 2 + 1];
                float mx = fmaxf(fmaxf(p0, p1), fmaxf(p2, p3));
                mx = fmaxf(mx, __shfl_xor_sync(0xffffffffu, mx, 1));
                mx = fmaxf(mx, __shfl_xor_sync(0xffffffffu, mx, 2));
                float e0 = __expf(p0 - mx), e1 = __expf(p1 - mx);
                float e2 = __expf(p2 - mx), e3 = __expf(p3 - mx);
                float den = e0 + e1 + e2 + e3;
                float bv_ = bvv[mf][hf];
                float acc = e0 * (dk[mf][2 * g][hf * 2] + bv_)
                          + e1 * (dk[mf][2 * g][hf * 2 + 1] + bv_)
                          + e2 * (dk[mf][2 * g + 1][hf * 2] + bv_)
                          + e3 * (dk[mf][2 * g + 1][hf * 2 + 1] + bv_);
                den += __shfl_xor_sync(0xffffffffu, den, 1);
                den += __shfl_xor_sync(0xffffffffu, den, 2);
                acc += __shfl_xor_sync(0xffffffffu, acc, 1);
                acc += __shfl_xor_sync(0xffffffffu, acc, 2);
                if ((L & 3) == 0) {
                    int n = tile * 4 + (wid >> 2) * 2 + g;
                    int o = obase + mf * 16 + (L >> 2) + hf * 8;
                    size_t oi = ((size_t)b * CC + o) * NN + n;
                    out[oi] = x_row[oi] + gm * (acc / den);
                }
            }
}

// ---------------------------------------------------------------------------
extern "C" void kernel_launch(void* const* d_in, const int* in_sizes, int n_in,
                              void* d_out, int out_size) {
    const float* x_row   = (const float*)d_in[0];
    const float* x_local = (const float*)d_in[1];
    const float* w0      = (const float*)d_in[2];
    const float* b0      = (const float*)d_in[3];
    const float* bn_g    = (const float*)d_in[4];
    const float* bn_b    = (const float*)d_in[5];
    const float* wq      = (const float*)d_in[6];
    const float* bq      = (const float*)d_in[7];
    const float* wk      = (const float*)d_in[8];
    const float* bk      = (const float*)d_in[9];
    const float* wv      = (const float*)d_in[10];
    const float* bv      = (const float*)d_in[11];
    const float* gamma1  = (const float*)d_in[12];
    float* out = (float*)d_out;

    cudaFuncSetAttribute(k_conv0, cudaFuncAttributeMaxDynamicSharedMemorySize, C_SMEM);
    cudaFuncSetAttribute(k_attn,  cudaFuncAttributeMaxDynamicSharedMemorySize, A_SMEM);

    k_conv0<<<dim3(TIL, BB), 256, C_SMEM>>>(x_local, w0, b0);
    k_stats<<<1, 1024>>>(bn_g, bn_b);
    k_attn<<<dim3(TIL, BB), 256, A_SMEM>>>(x_row, wq, bq, wk, bk, wv, bv, gamma1, out);
}

// round 16
// speedup vs baseline: 1.1674x; 1.1674x over previous
#include <cuda_runtime.h>
#include <cuda_bf16.h>

typedef unsigned int u32;
typedef unsigned long long u64;

#define BB   8
#define CC   128
#define NN   2000
#define NKS  32000
#define CTIL 500          // conv0 s-tiles of 64 per batch
#define CTSI 64
#define ATIL 250          // attn s-tiles of 128 per batch
#define ATSI 128

// conv0 smem (bytes): W 256B-pitch full tiles, x 128B-pitch tiles
#define C_WH   0
#define C_WL   32768
#define C_XH   65536
#define C_XL   81920
#define C_BUF  0                   // fp32 [64][132] = 33792, overlaps dead W
#define C_S4   98304               // fp32 [4][128] = 2048
#define C_SMEM (98304 + 2048)

// attn smem: full 256B-pitch tiles
#define A_QH   0
#define A_QL   32768
#define A_KH   65536
#define A_KL   98304
#define A_HH   131072
#define A_HL   163840
#define A_SMEM 196608

// Scratch (device globals: allocation-free rule)
__device__ __align__(16) float g_h[(size_t)BB * NKS * CC];   // h as [b][s][c]
__device__ __align__(16) unsigned char g_wp[8 * 32768];      // prepped bf16 hi/lo weight tiles
__device__ float g_psum[BB * CTIL * CC];
__device__ float g_psq [BB * CTIL * CC];
__device__ __align__(16) float g_scale[BB * CC];
__device__ __align__(16) float g_shift[BB * CC];

// ---------------------------------------------------------------------------
// helpers
// ---------------------------------------------------------------------------
__device__ __forceinline__ u32 smem_u32(const void* p) {
    u32 a;
    asm("{ .reg .u64 t; cvta.to.shared.u64 t, %1; cvt.u32.u64 %0, t; }" : "=r"(a) : "l"(p));
    return a;
}

// a -> low half, b -> high half; hi/lo bf16 split of the fp32 pair
__device__ __forceinline__ void split2(float a, float b, u32& hi, u32& lo) {
    u32 h;
    asm("cvt.rn.bf16x2.f32 %0, %1, %2;" : "=r"(h) : "f"(b), "f"(a));
    float fa = __uint_as_float(h << 16);
    float fb = __uint_as_float(h & 0xffff0000u);
    float la = a - fa, lb = b - fb;
    asm("cvt.rn.bf16x2.f32 %0, %1, %2;" : "=r"(lo) : "f"(lb), "f"(la));
    hi = h;
}

__device__ __forceinline__ void cp16(u32 sdst, const void* gsrc) {
    asm volatile("cp.async.cg.shared.global [%0], [%1], 16;" :: "r"(sdst), "l"(gsrc));
}
__device__ __forceinline__ void cp_wait_all() {
    asm volatile("cp.async.commit_group;");
    asm volatile("cp.async.wait_group 0;" ::: "memory");
}

__device__ __forceinline__ void ldsm4(u32 r[4], u32 addr) {
    asm volatile("ldmatrix.sync.aligned.m8n8.x4.shared.b16 {%0,%1,%2,%3}, [%4];"
        : "=r"(r[0]), "=r"(r[1]), "=r"(r[2]), "=r"(r[3]) : "r"(addr));
}
__device__ __forceinline__ void ldsm4t(u32 r[4], u32 addr) {
    asm volatile("ldmatrix.sync.aligned.m8n8.x4.trans.shared.b16 {%0,%1,%2,%3}, [%4];"
        : "=r"(r[0]), "=r"(r[1]), "=r"(r[2]), "=r"(r[3]) : "r"(addr));
}
__device__ __forceinline__ void mma16816(float d[4], const u32 a[4], const u32 b[2]) {
    asm volatile("mma.sync.aligned.m16n8k16.row.col.f32.bf16.bf16.f32 "
        "{%0,%1,%2,%3}, {%4,%5,%6,%7}, {%8,%9}, {%0,%1,%2,%3};"
        : "+f"(d[0]), "+f"(d[1]), "+f"(d[2]), "+f"(d[3])
        : "r"(a[0]), "r"(a[1]), "r"(a[2]), "r"(a[3]), "r"(b[0]), "r"(b[1]));
}

// ---------------------------------------------------------------------------
// Kernel 0: prep weights -> bf16 hi/lo tiles in final swizzled layout (gmem).
// grid (4), 256 threads. Order: w0,wq,wk,wv; per weight: hi (32KB) then lo.
// ---------------------------------------------------------------------------
__global__ void k_prep(const float* __restrict__ w0, const float* __restrict__ wq,
                       const float* __restrict__ wk, const float* __restrict__ wv) {
    int w = blockIdx.x, t = threadIdx.x;
    const float* src = (w == 0) ? w0 : (w == 1) ? wq : (w == 2) ? wk : wv;
    unsigned char* dhi = g_wp + (size_t)w * 65536;
    unsigned char* dlo = dhi + 32768;
#pragma unroll
    for (int i = 0; i < 16; i++) {
        int f = i * 256 + t;
        int o = f >> 5, c0 = (f & 31) << 2;
        float4 v = reinterpret_cast<const float4*>(src)[f];
        u32 h0, l0, h1, l1;
        split2(v.x, v.y, h0, l0);
        split2(v.z, v.w, h1, l1);
        u32 ad = (u32)(o * 256) + (u32)((c0 * 2) ^ ((o & 7) << 4));
        *reinterpret_cast<u64*>(dhi + ad) = ((u64)h1 << 32) | h0;
        *reinterpret_cast<u64*>(dlo + ad) = ((u64)l1 << 32) | l0;
    }
}

// ---------------------------------------------------------------------------
// Kernel 1: h = W0 @ x + b0 via mma.sync (bf16-split), h stored [b][s][c];
// per-tile partial sum/sumsq. grid (500, 8), 256 threads, 2 CTAs/SM.
// Weights arrive via cp.async from prepped tiles.
// ---------------------------------------------------------------------------
__global__ __launch_bounds__(256, 2) void k_conv0(const float* __restrict__ x,
                                                  const float* __restrict__ b0) {
    extern __shared__ char smc[];
    u32 sm32 = smem_u32(smc);
    int t = threadIdx.x, wid = t >> 5, L = t & 31;
    int b = blockIdx.y, tile = blockIdx.x;
    int s0 = tile * CTSI;

    // W0 hi+lo: 64KB linear cp.async (layout already final)
#pragma unroll
    for (int i = 0; i < 16; i++) {
        int idx = i * 256 + t;
        cp16(sm32 + C_WH + idx * 16, g_wp + idx * 16);
    }

    // B = x tile [c][s0..s0+64), 128B pitch, pairs along s
    {
        int c = t >> 1, q = t & 1;
        const float4* src = reinterpret_cast<const float4*>(
            x + ((size_t)b * CC + c) * NKS + s0) + q * 8;
        u32 rowbase = (u32)(c * 128);
        u32 xm = (u32)((c & 7) << 4);
#pragma unroll
        for (int i = 0; i < 8; i++) {
            float4 v = src[i];
            u32 h0, l0, h1, l1;
            split2(v.x, v.y, h0, l0);
            split2(v.z, v.w, h1, l1);
            u32 ad = rowbase + (((u32)(q * 64 + i * 8)) ^ xm);
            *reinterpret_cast<u64*>(smc + C_XH + ad) = ((u64)h1 << 32) | h0;
            *reinterpret_cast<u64*>(smc + C_XL + ad) = ((u64)l1 << 32) | l0;
        }
    }
    cp_wait_all();
    __syncthreads();

    int obase = (wid & 3) * 32, sbase = (wid >> 2) * 32;
    int m = L >> 3;
    int rA_off = (m & 1) * 8 + (L & 7);   // A row offset within 16
    int kbA_off = (m >> 1) * 16;          // A k-byte offset
    int krB_off = (m & 1) * 8 + (L & 7);  // B (trans) k-row offset within 16
    int cbB = sbase * 2 + (m >> 1) * 16;  // B col-byte base

    float d[2][4][4];
#pragma unroll
    for (int mf = 0; mf < 2; mf++)
#pragma unroll
        for (int nf = 0; nf < 4; nf++)
#pragma unroll
            for (int j = 0; j < 4; j++) d[mf][nf][j] = 0.f;

#pragma unroll
    for (int ks = 0; ks < 8; ks++) {
        u32 bh[4][2], bl[4][2];
        int krow = ks * 16 + krB_off;
        u32 rowb = (u32)(krow * 128);
        u32 xm = (u32)((krow & 7) << 4);
#pragma unroll
        for (int np = 0; np < 2; np++) {
            u32 ad = rowb + (((u32)(cbB + np * 32)) ^ xm);
            u32 r[4];
            ldsm4t(r, sm32 + C_XH + ad);
            bh[np * 2][0] = r[0]; bh[np * 2][1] = r[1];
            bh[np * 2 + 1][0] = r[2]; bh[np * 2 + 1][1] = r[3];
            ldsm4t(r, sm32 + C_XL + ad);
            bl[np * 2][0] = r[0]; bl[np * 2][1] = r[1];
            bl[np * 2 + 1][0] = r[2]; bl[np * 2 + 1][1] = r[3];
        }
        u32 ah[2][4], al[2][4];
#pragma unroll
        for (int mf = 0; mf < 2; mf++) {
            int row = obase + mf * 16 + rA_off;
            u32 ad = (u32)(row * 256) + (u32)((ks * 32 + kbA_off) ^ ((row & 7) << 4));
            ldsm4(ah[mf], sm32 + C_WH + ad);
            ldsm4(al[mf], sm32 + C_WL + ad);
        }
#pragma unroll
        for (int mf = 0; mf < 2; mf++)
#pragma unroll
            for (int nf = 0; nf < 4; nf++) {
                mma16816(d[mf][nf], ah[mf], bh[nf]);
                mma16816(d[mf][nf], ah[mf], bl[nf]);
                mma16816(d[mf][nf], al[mf], bh[nf]);
            }
    }
    __syncthreads();   // W/X dead; buf overlaps them

    // stage D[o][s] -> buf[s][o] (pitch 132)
    float* buf = reinterpret_cast<float*>(smc + C_BUF);
#pragma unroll
    for (int mf = 0; mf < 2; mf++)
#pragma unroll
        for (int nf = 0; nf < 4; nf++)
#pragma unroll
            for (int j = 0; j < 4; j++) {
                int srow = sbase + nf * 8 + (L & 3) * 2 + (j & 1);
                int o = obase + mf * 16 + (L >> 2) + (j >> 1) * 8;
                buf[srow * 132 + o] = d[mf][nf][j];
            }
    __syncthreads();

    // read buf rows, add bias, write g_h[b][s][c] coalesced + stats partials
    {
        float* s4 = reinterpret_cast<float*>(smc + C_S4);
        int c = t & 127, sq = t >> 7;          // sq in {0,1}
        float bias = b0[c];
        float sacc = 0.f, qacc = 0.f;
#pragma unroll 4
        for (int i = 0; i < 32; i++) {
            int srow = sq * 32 + i;
            float v = buf[srow * 132 + c] + bias;
            g_h[((size_t)b * NKS + s0 + srow) * CC + c] = v;
            sacc += v; qacc += v * v;
        }
        s4[sq * 128 + c] = sacc;
        s4[256 + sq * 128 + c] = qacc;
        __syncthreads();
        if (t < 128) {
            float s = s4[t] + s4[128 + t];
            float q = s4[256 + t] + s4[384 + t];
            int pi = (b * CTIL + tile) * CC + t;
            g_psum[pi] = s;
            g_psq[pi] = q;
        }
    }
}

// ---------------------------------------------------------------------------
// Kernel 2: collapse IN + BN -> per-(b,c) affine. After IN, per-(b,c) mean==0
// and var==v/(v+eps_in); BN batch mean==0, BN var==mean_b[v/(v+eps_in)].
// ---------------------------------------------------------------------------
__global__ void k_stats(const float* __restrict__ bn_g, const float* __restrict__ bn_b) {
    __shared__ float rmat[BB][CC];
    __shared__ float bsc[CC];
    int t = threadIdx.x;
    int b = t >> 7, c = t & 127;

    float s = 0.f, q = 0.f;
    for (int i = 0; i < CTIL; i++) {
        int idx = (b * CTIL + i) * CC + c;
        s += g_psum[idx];
        q += g_psq[idx];
    }
    const float inv_n = 1.0f / (float)NKS;
    float mu  = s * inv_n;
    float var = fmaxf(q * inv_n - mu * mu, 0.f);
    rmat[b][c] = var / (var + 1e-3f);
    __syncthreads();
    if (t < CC) {
        float ss = 0.f;
#pragma unroll
        for (int i = 0; i < BB; i++) ss += rmat[i][t];
        bsc[t] = rsqrtf(ss * (1.0f / BB) + 1e-5f);
    }
    __syncthreads();
    float scale = rsqrtf(var + 1e-3f) * bsc[c] * bn_g[c];
    g_scale[b * CC + c] = scale;
    g_shift[b * CC + c] = bn_b[c] - mu * scale;
}

// ---------------------------------------------------------------------------
// Kernel 3: hn = relu(affine(h)); q,k,v GEMMs via mma.sync (bf16-split);
// softmax over K=16 via quad shfl; residual. grid (250, 8), 512 threads.
// Weights via cp.async from prepped tiles (no per-block fp32 staging).
// ---------------------------------------------------------------------------
__global__ __launch_bounds__(512, 1) void k_attn(
    const float* __restrict__ x_row,
    const float* __restrict__ bq, const float* __restrict__ bk,
    const float* __restrict__ bv,
    const float* __restrict__ gamma1, float* __restrict__ out) {
    extern __shared__ char smc[];
    u32 sm32 = smem_u32(smc);
    int t = threadIdx.x, wid = t >> 5, L = t & 31;
    int b = blockIdx.y, tile = blockIdx.x;
    int s0 = tile * ATSI;

    // Wq hi/lo + Wk hi/lo: 128KB linear cp.async from g_wp + 64KB
#pragma unroll
    for (int i = 0; i < 16; i++) {
        int idx = i * 512 + t;
        cp16(sm32 + A_QH + idx * 16, g_wp + 65536 + idx * 16);
    }

    // hn tile [s][c] (128 rows x 256B): read g_h[b][s][c], affine+relu, split
    {
        int srow = t >> 2, cb = (t & 3) * 32;
        const float4* hp  = reinterpret_cast<const float4*>(
            g_h + ((size_t)b * NKS + s0 + srow) * CC + cb);
        const float4* scp = reinterpret_cast<const float4*>(g_scale + b * CC + cb);
        const float4* shp = reinterpret_cast<const float4*>(g_shift + b * CC + cb);
        u32 rowb = (u32)(srow * 256);
        u32 xm = (u32)((srow & 7) << 4);
#pragma unroll
        for (int i = 0; i < 8; i++) {
            float4 v  = hp[i];
            float4 sc = scp[i];
            float4 sh = shp[i];
            v.x = fmaxf(fmaf(v.x, sc.x, sh.x), 0.f);
            v.y = fmaxf(fmaf(v.y, sc.y, sh.y), 0.f);
            v.z = fmaxf(fmaf(v.z, sc.z, sh.z), 0.f);
            v.w = fmaxf(fmaf(v.w, sc.w, sh.w), 0.f);
            u32 h0, l0, h1, l1;
            split2(v.x, v.y, h0, l0);
            split2(v.z, v.w, h1, l1);
            u32 ad = rowb + (((u32)(cb * 2 + i * 8)) ^ xm);
            *reinterpret_cast<u64*>(smc + A_HH + ad) = ((u64)h1 << 32) | h0;
            *reinterpret_cast<u64*>(smc + A_HL + ad) = ((u64)l1 << 32) | l0;
        }
    }
    cp_wait_all();
    __syncthreads();

    int obase = (wid & 3) * 32, sbase = (wid >> 2) * 32;
    int m = L >> 3;
    int rA_off = (m & 1) * 8 + (L & 7);
    int kbA_off = (m >> 1) * 16;
    int nrB_off = ((m >> 1) & 1) * 8 + (L & 7);  // B non-trans: n-row offset
    int kbB_off = (m & 1) * 16;

    float dq[2][4][4], dk[2][4][4];
#pragma unroll
    for (int mf = 0; mf < 2; mf++)
#pragma unroll
        for (int nf = 0; nf < 4; nf++)
#pragma unroll
            for (int j = 0; j < 4; j++) { dq[mf][nf][j] = 0.f; dk[mf][nf][j] = 0.f; }

    // phase 1: q and k GEMMs, shared B loads
#pragma unroll
    for (int ks = 0; ks < 8; ks++) {
        u32 bh[4][2], bl[4][2];
#pragma unroll
        for (int np = 0; np < 2; np++) {
            int nrow = sbase + np * 16 + nrB_off;
            u32 ad = (u32)(nrow * 256) + (u32)((ks * 32 + kbB_off) ^ ((nrow & 7) << 4));
            u32 r[4];
            ldsm4(r, sm32 + A_HH + ad);
            bh[np * 2][0] = r[0]; bh[np * 2][1] = r[1];
            bh[np * 2 + 1][0] = r[2]; bh[np * 2 + 1][1] = r[3];
            ldsm4(r, sm32 + A_HL + ad);
            bl[np * 2][0] = r[0]; bl[np * 2][1] = r[1];
            bl[np * 2 + 1][0] = r[2]; bl[np * 2 + 1][1] = r[3];
        }
        u32 ah[2][4], al[2][4];
#pragma unroll
        for (int mf = 0; mf < 2; mf++) {
            int row = obase + mf * 16 + rA_off;
            u32 ad = (u32)(row * 256) + (u32)((ks * 32 + kbA_off) ^ ((row & 7) << 4));
            ldsm4(ah[mf], sm32 + A_QH + ad);
            ldsm4(al[mf], sm32 + A_QL + ad);
        }
#pragma unroll
        for (int mf = 0; mf < 2; mf++)
#pragma unroll
            for (int nf = 0; nf < 4; nf++) {
                mma16816(dq[mf][nf], ah[mf], bh[nf]);
                mma16816(dq[mf][nf], ah[mf], bl[nf]);
                mma16816(dq[mf][nf], al[mf], bh[nf]);
            }
#pragma unroll
        for (int mf = 0; mf < 2; mf++) {
            int row = obase + mf * 16 + rA_off;
            u32 ad = (u32)(row * 256) + (u32)((ks * 32 + kbA_off) ^ ((row & 7) << 4));
            ldsm4(ah[mf], sm32 + A_KH + ad);
            ldsm4(al[mf], sm32 + A_KL + ad);
        }
#pragma unroll
        for (int mf = 0; mf < 2; mf++)
#pragma unroll
            for (int nf = 0; nf < 4; nf++) {
                mma16816(dk[mf][nf], ah[mf], bh[nf]);
                mma16816(dk[mf][nf], ah[mf], bl[nf]);
                mma16816(dk[mf][nf], al[mf], bh[nf]);
            }
    }

    // p = (q+bq)*(k+bk) in-place into dq
    float bqv[2][2], bkv[2][2], bvv[2][2];
#pragma unroll
    for (int mf = 0; mf < 2; mf++)
#pragma unroll
        for (int hf = 0; hf < 2; hf++) {
            int o = obase + mf * 16 + (L >> 2) + hf * 8;
            bqv[mf][hf] = bq[o]; bkv[mf][hf] = bk[o]; bvv[mf][hf] = bv[o];
        }
#pragma unroll
    for (int mf = 0; mf < 2; mf++)
#pragma unroll
        for (int nf = 0; nf < 4; nf++)
#pragma unroll
            for (int j = 0; j < 4; j++) {
                int hf = j >> 1;
                dq[mf][nf][j] = (dq[mf][nf][j] + bqv[mf][hf]) * (dk[mf][nf][j] + bkv[mf][hf]);
            }

    __syncthreads();
    // Wv hi/lo: 64KB cp.async over Wq buffers
#pragma unroll
    for (int i = 0; i < 8; i++) {
        int idx = i * 512 + t;
        cp16(sm32 + A_QH + idx * 16, g_wp + 196608 + idx * 16);
    }
    cp_wait_all();
    __syncthreads();

    // phase 2: v GEMM (dk reused as accumulator)
#pragma unroll
    for (int mf = 0; mf < 2; mf++)
#pragma unroll
        for (int nf = 0; nf < 4; nf++)
#pragma unroll
            for (int j = 0; j < 4; j++) dk[mf][nf][j] = 0.f;

#pragma unroll
    for (int ks = 0; ks < 8; ks++) {
        u32 bh[4][2], bl[4][2];
#pragma unroll
        for (int np = 0; np < 2; np++) {
            int nrow = sbase + np * 16 + nrB_off;
            u32 ad = (u32)(nrow * 256) + (u32)((ks * 32 + kbB_off) ^ ((nrow & 7) << 4));
            u32 r[4];
            ldsm4(r, sm32 + A_HH + ad);
            bh[np * 2][0] = r[0]; bh[np * 2][1] = r[1];
            bh[np * 2 + 1][0] = r[2]; bh[np * 2 + 1][1] = r[3];
            ldsm4(r, sm32 + A_HL + ad);
            bl[np * 2][0] = r[0]; bl[np * 2][1] = r[1];
            bl[np * 2 + 1][0] = r[2]; bl[np * 2 + 1][1] = r[3];
        }
        u32 ah[2][4], al[2][4];
#pragma unroll
        for (int mf = 0; mf < 2; mf++) {
            int row = obase + mf * 16 + rA_off;
            u32 ad = (u32)(row * 256) + (u32)((ks * 32 + kbA_off) ^ ((row & 7) << 4));
            ldsm4(ah[mf], sm32 + A_QH + ad);
            ldsm4(al[mf], sm32 + A_QL + ad);
        }
#pragma unroll
        for (int mf = 0; mf < 2; mf++)
#pragma unroll
            for (int nf = 0; nf < 4; nf++) {
                mma16816(dk[mf][nf], ah[mf], bh[nf]);
                mma16816(dk[mf][nf], ah[mf], bl[nf]);
                mma16816(dk[mf][nf], al[mf], bh[nf]);
            }
    }

    // epilogue: softmax over 16-s groups (quad shfl) + weighted V + residual
    float gm = gamma1[0];
#pragma unroll
    for (int mf = 0; mf < 2; mf++)
#pragma unroll
        for (int hf = 0; hf < 2; hf++)
#pragma unroll
            for (int g = 0; g < 2; g++) {
                float p0 = dq[mf][2 * g][hf * 2],     p1 = dq[mf][2 * g][hf * 2 + 1];
                float p2 = dq[mf][2 * g + 1][hf * 2], p3 = dq[mf][2 * g + 1][hf * 2 + 1];
                float mx = fmaxf(fmaxf(p0, p1), fmaxf(p2, p3));
                mx = fmaxf(mx, __shfl_xor_sync(0xffffffffu, mx, 1));
                mx = fmaxf(mx, __shfl_xor_sync(0xffffffffu, mx, 2));
                float e0 = __expf(p0 - mx), e1 = __expf(p1 - mx);
                float e2 = __expf(p2 - mx), e3 = __expf(p3 - mx);
                float den = e0 + e1 + e2 + e3;
                float bv_ = bvv[mf][hf];
                float acc = e0 * (dk[mf][2 * g][hf * 2] + bv_)
                          + e1 * (dk[mf][2 * g][hf * 2 + 1] + bv_)
                          + e2 * (dk[mf][2 * g + 1][hf * 2] + bv_)
                          + e3 * (dk[mf][2 * g + 1][hf * 2 + 1] + bv_);
                den += __shfl_xor_sync(0xffffffffu, den, 1);
                den += __shfl_xor_sync(0xffffffffu, den, 2);
                acc += __shfl_xor_sync(0xffffffffu, acc, 1);
                acc += __shfl_xor_sync(0xffffffffu, acc, 2);
                if ((L & 3) == 0) {
                    int n = tile * 8 + (wid >> 2) * 2 + g;
                    int o = obase + mf * 16 + (L >> 2) + hf * 8;
                    size_t oi = ((size_t)b * CC + o) * NN + n;
                    out[oi] = x_row[oi] + gm * (acc / den);
                }
            }
}

// ---------------------------------------------------------------------------
extern "C" void kernel_launch(void* const* d_in, const int* in_sizes, int n_in,
                              void* d_out, int out_size) {
    const float* x_row   = (const float*)d_in[0];
    const float* x_local = (const float*)d_in[1];
    const float* w0      = (const float*)d_in[2];
    const float* b0      = (const float*)d_in[3];
    const float* bn_g    = (const float*)d_in[4];
    const float* bn_b    = (const float*)d_in[5];
    const float* wq      = (const float*)d_in[6];
    const float* bq      = (const float*)d_in[7];
    const float* wk      = (const float*)d_in[8];
    const float* bk      = (const float*)d_in[9];
    const float* wv      = (const float*)d_in[10];
    const float* bv      = (const float*)d_in[11];
    const float* gamma1  = (const float*)d_in[12];
    float* out = (float*)d_out;

    cudaFuncSetAttribute(k_conv0, cudaFuncAttributeMaxDynamicSharedMemorySize, C_SMEM);
    cudaFuncSetAttribute(k_attn,  cudaFuncAttributeMaxDynamicSharedMemorySize, A_SMEM);

    k_prep<<<4, 256>>>(w0, wq, wk, wv);
    k_conv0<<<dim3(CTIL, BB), 256, C_SMEM>>>(x_local, b0);
    k_stats<<<1, 1024>>>(bn_g, bn_b);
    k_attn<<<dim3(ATIL, BB), 512, A_SMEM>>>(x_row, bq, bk, bv, gamma1, out);
}

// round 17
// speedup vs baseline: 1.2058x; 1.0330x over previous
#include <cuda_runtime.h>
#include <cuda_bf16.h>

typedef unsigned int u32;
typedef unsigned long long u64;

#define BB   8
#define CC   128
#define NN   2000
#define NKS  32000
#define CTIL 500          // conv0 s-tiles of 64 per batch
#define CTSI 64
#define AUNITS 4000       // attn units: 8 batches x 500 tiles of 64 s
#define APER  148         // persistent attn blocks

// conv0 smem (bytes): W 256B-pitch full tiles, x 128B-pitch tiles
#define C_WH   0
#define C_WL   32768
#define C_XH   65536
#define C_XL   81920
#define C_BUF  0                   // fp32 [64][132] = 33792, overlaps dead W
#define C_S4   98304               // fp32 [4][128] = 2048
#define C_SMEM (98304 + 2048)

// attn smem: Wq,Wk,Wv hi/lo resident (192KB) + h tile 32KB
#define A_QH   0
#define A_QL   32768
#define A_KH   65536
#define A_KL   98304
#define A_VH   131072
#define A_VL   163840
#define A_HH   196608
#define A_HL   212992
#define A_SMEM 229376

// Scratch (device globals: allocation-free rule)
__device__ __align__(16) float g_h[(size_t)BB * NKS * CC];   // h as [b][s][c]
__device__ __align__(16) unsigned char g_wp[8 * 32768];      // prepped bf16 hi/lo weight tiles
__device__ float g_psum[BB * CTIL * CC];
__device__ float g_psq [BB * CTIL * CC];
__device__ __align__(16) float g_scale[BB * CC];
__device__ __align__(16) float g_shift[BB * CC];

// ---------------------------------------------------------------------------
// helpers
// ---------------------------------------------------------------------------
__device__ __forceinline__ u32 smem_u32(const void* p) {
    u32 a;
    asm("{ .reg .u64 t; cvta.to.shared.u64 t, %1; cvt.u32.u64 %0, t; }" : "=r"(a) : "l"(p));
    return a;
}

// a -> low half, b -> high half; hi/lo bf16 split of the fp32 pair
__device__ __forceinline__ void split2(float a, float b, u32& hi, u32& lo) {
    u32 h;
    asm("cvt.rn.bf16x2.f32 %0, %1, %2;" : "=r"(h) : "f"(b), "f"(a));
    float fa = __uint_as_float(h << 16);
    float fb = __uint_as_float(h & 0xffff0000u);
    float la = a - fa, lb = b - fb;
    asm("cvt.rn.bf16x2.f32 %0, %1, %2;" : "=r"(lo) : "f"(lb), "f"(la));
    hi = h;
}

__device__ __forceinline__ void cp16(u32 sdst, const void* gsrc) {
    asm volatile("cp.async.cg.shared.global [%0], [%1], 16;" :: "r"(sdst), "l"(gsrc));
}
__device__ __forceinline__ void cp_commit() {
    asm volatile("cp.async.commit_group;");
}
__device__ __forceinline__ void cp_wait0() {
    asm volatile("cp.async.wait_group 0;" ::: "memory");
}

__device__ __forceinline__ void ldsm4(u32 r[4], u32 addr) {
    asm volatile("ldmatrix.sync.aligned.m8n8.x4.shared.b16 {%0,%1,%2,%3}, [%4];"
        : "=r"(r[0]), "=r"(r[1]), "=r"(r[2]), "=r"(r[3]) : "r"(addr));
}
__device__ __forceinline__ void ldsm4t(u32 r[4], u32 addr) {
    asm volatile("ldmatrix.sync.aligned.m8n8.x4.trans.shared.b16 {%0,%1,%2,%3}, [%4];"
        : "=r"(r[0]), "=r"(r[1]), "=r"(r[2]), "=r"(r[3]) : "r"(addr));
}
__device__ __forceinline__ void mma16816(float d[4], const u32 a[4], const u32 b[2]) {
    asm volatile("mma.sync.aligned.m16n8k16.row.col.f32.bf16.bf16.f32 "
        "{%0,%1,%2,%3}, {%4,%5,%6,%7}, {%8,%9}, {%0,%1,%2,%3};"
        : "+f"(d[0]), "+f"(d[1]), "+f"(d[2]), "+f"(d[3])
        : "r"(a[0]), "r"(a[1]), "r"(a[2]), "r"(a[3]), "r"(b[0]), "r"(b[1]));
}

// ---------------------------------------------------------------------------
// Kernel 0: prep weights -> bf16 hi/lo tiles in final swizzled layout (gmem).
// grid (4), 256 threads. Order: w0,wq,wk,wv; per weight: hi (32KB) then lo.
// ---------------------------------------------------------------------------
__global__ void k_prep(const float* __restrict__ w0, const float* __restrict__ wq,
                       const float* __restrict__ wk, const float* __restrict__ wv) {
    int w = blockIdx.x, t = threadIdx.x;
    const float* src = (w == 0) ? w0 : (w == 1) ? wq : (w == 2) ? wk : wv;
    unsigned char* dhi = g_wp + (size_t)w * 65536;
    unsigned char* dlo = dhi + 32768;
#pragma unroll
    for (int i = 0; i < 16; i++) {
        int f = i * 256 + t;
        int o = f >> 5, c0 = (f & 31) << 2;
        float4 v = reinterpret_cast<const float4*>(src)[f];
        u32 h0, l0, h1, l1;
        split2(v.x, v.y, h0, l0);
        split2(v.z, v.w, h1, l1);
        u32 ad = (u32)(o * 256) + (u32)((c0 * 2) ^ ((o & 7) << 4));
        *reinterpret_cast<u64*>(dhi + ad) = ((u64)h1 << 32) | h0;
        *reinterpret_cast<u64*>(dlo + ad) = ((u64)l1 << 32) | l0;
    }
}

// ---------------------------------------------------------------------------
// Kernel 1: h = W0 @ x + b0 via mma.sync (bf16-split), h stored [b][s][c];
// per-tile partial sum/sumsq. grid (500, 8), 256 threads, 2 CTAs/SM.
// ---------------------------------------------------------------------------
__global__ __launch_bounds__(256, 2) void k_conv0(const float* __restrict__ x,
                                                  const float* __restrict__ b0) {
    extern __shared__ char smc[];
    u32 sm32 = smem_u32(smc);
    int t = threadIdx.x, wid = t >> 5, L = t & 31;
    int b = blockIdx.y, tile = blockIdx.x;
    int s0 = tile * CTSI;

    // W0 hi+lo: 64KB linear cp.async (layout already final)
#pragma unroll
    for (int i = 0; i < 16; i++) {
        int idx = i * 256 + t;
        cp16(sm32 + C_WH + idx * 16, g_wp + idx * 16);
    }
    cp_commit();

    // B = x tile [c][s0..s0+64), 128B pitch, pairs along s
    {
        int c = t >> 1, q = t & 1;
        const float4* src = reinterpret_cast<const float4*>(
            x + ((size_t)b * CC + c) * NKS + s0) + q * 8;
        u32 rowbase = (u32)(c * 128);
        u32 xm = (u32)((c & 7) << 4);
#pragma unroll
        for (int i = 0; i < 8; i++) {
            float4 v = src[i];
            u32 h0, l0, h1, l1;
            split2(v.x, v.y, h0, l0);
            split2(v.z, v.w, h1, l1);
            u32 ad = rowbase + (((u32)(q * 64 + i * 8)) ^ xm);
            *reinterpret_cast<u64*>(smc + C_XH + ad) = ((u64)h1 << 32) | h0;
            *reinterpret_cast<u64*>(smc + C_XL + ad) = ((u64)l1 << 32) | l0;
        }
    }
    cp_wait0();
    __syncthreads();

    int obase = (wid & 3) * 32, sbase = (wid >> 2) * 32;
    int m = L >> 3;
    int rA_off = (m & 1) * 8 + (L & 7);   // A row offset within 16
    int kbA_off = (m >> 1) * 16;          // A k-byte offset
    int krB_off = (m & 1) * 8 + (L & 7);  // B (trans) k-row offset within 16
    int cbB = sbase * 2 + (m >> 1) * 16;  // B col-byte base

    float d[2][4][4];
#pragma unroll
    for (int mf = 0; mf < 2; mf++)
#pragma unroll
        for (int nf = 0; nf < 4; nf++)
#pragma unroll
            for (int j = 0; j < 4; j++) d[mf][nf][j] = 0.f;

#pragma unroll
    for (int ks = 0; ks < 8; ks++) {
        u32 bh[4][2], bl[4][2];
        int krow = ks * 16 + krB_off;
        u32 rowb = (u32)(krow * 128);
        u32 xm = (u32)((krow & 7) << 4);
#pragma unroll
        for (int np = 0; np < 2; np++) {
            u32 ad = rowb + (((u32)(cbB + np * 32)) ^ xm);
            u32 r[4];
            ldsm4t(r, sm32 + C_XH + ad);
            bh[np * 2][0] = r[0]; bh[np * 2][1] = r[1];
            bh[np * 2 + 1][0] = r[2]; bh[np * 2 + 1][1] = r[3];
            ldsm4t(r, sm32 + C_XL + ad);
            bl[np * 2][0] = r[0]; bl[np * 2][1] = r[1];
            bl[np * 2 + 1][0] = r[2]; bl[np * 2 + 1][1] = r[3];
        }
        u32 ah[2][4], al[2][4];
#pragma unroll
        for (int mf = 0; mf < 2; mf++) {
            int row = obase + mf * 16 + rA_off;
            u32 ad = (u32)(row * 256) + (u32)((ks * 32 + kbA_off) ^ ((row & 7) << 4));
            ldsm4(ah[mf], sm32 + C_WH + ad);
            ldsm4(al[mf], sm32 + C_WL + ad);
        }
#pragma unroll
        for (int mf = 0; mf < 2; mf++)
#pragma unroll
            for (int nf = 0; nf < 4; nf++) {
                mma16816(d[mf][nf], ah[mf], bh[nf]);
                mma16816(d[mf][nf], ah[mf], bl[nf]);
                mma16816(d[mf][nf], al[mf], bh[nf]);
            }
    }
    __syncthreads();   // W/X dead; buf overlaps them

    // stage D[o][s] -> buf[s][o] (pitch 132)
    float* buf = reinterpret_cast<float*>(smc + C_BUF);
#pragma unroll
    for (int mf = 0; mf < 2; mf++)
#pragma unroll
        for (int nf = 0; nf < 4; nf++)
#pragma unroll
            for (int j = 0; j < 4; j++) {
                int srow = sbase + nf * 8 + (L & 3) * 2 + (j & 1);
                int o = obase + mf * 16 + (L >> 2) + (j >> 1) * 8;
                buf[srow * 132 + o] = d[mf][nf][j];
            }
    __syncthreads();

    // read buf rows, add bias, write g_h[b][s][c] coalesced + stats partials
    {
        float* s4 = reinterpret_cast<float*>(smc + C_S4);
        int c = t & 127, sq = t >> 7;          // sq in {0,1}
        float bias = b0[c];
        float sacc = 0.f, qacc = 0.f;
#pragma unroll 4
        for (int i = 0; i < 32; i++) {
            int srow = sq * 32 + i;
            float v = buf[srow * 132 + c] + bias;
            g_h[((size_t)b * NKS + s0 + srow) * CC + c] = v;
            sacc += v; qacc += v * v;
        }
        s4[sq * 128 + c] = sacc;
        s4[256 + sq * 128 + c] = qacc;
        __syncthreads();
        if (t < 128) {
            float s = s4[t] + s4[128 + t];
            float q = s4[256 + t] + s4[384 + t];
            int pi = (b * CTIL + tile) * CC + t;
            g_psum[pi] = s;
            g_psq[pi] = q;
        }
    }
}

// ---------------------------------------------------------------------------
// Kernel 2: collapse IN + BN -> per-(b,c) affine. After IN, per-(b,c) mean==0
// and var==v/(v+eps_in); BN batch mean==0, BN var==mean_b[v/(v+eps_in)].
// ---------------------------------------------------------------------------
__global__ void k_stats(const float* __restrict__ bn_g, const float* __restrict__ bn_b) {
    __shared__ float rmat[BB][CC];
    __shared__ float bsc[CC];
    int t = threadIdx.x;
    int b = t >> 7, c = t & 127;

    float s = 0.f, q = 0.f;
    for (int i = 0; i < CTIL; i++) {
        int idx = (b * CTIL + i) * CC + c;
        s += g_psum[idx];
        q += g_psq[idx];
    }
    const float inv_n = 1.0f / (float)NKS;
    float mu  = s * inv_n;
    float var = fmaxf(q * inv_n - mu * mu, 0.f);
    rmat[b][c] = var / (var + 1e-3f);
    __syncthreads();
    if (t < CC) {
        float ss = 0.f;
#pragma unroll
        for (int i = 0; i < BB; i++) ss += rmat[i][t];
        bsc[t] = rsqrtf(ss * (1.0f / BB) + 1e-5f);
    }
    __syncthreads();
    float scale = rsqrtf(var + 1e-3f) * bsc[c] * bn_g[c];
    g_scale[b * CC + c] = scale;
    g_shift[b * CC + c] = bn_b[c] - mu * scale;
}

// ---------------------------------------------------------------------------
// Kernel 3: PERSISTENT attn. Wq/Wk/Wv hi+lo resident in smem (192KB, loaded
// once per block). Each block loops over (b, 64-s tile) units: stage hn tile,
// run q,k,v GEMMs in one pass (bf16-split), warp-local softmax, residual.
// grid (148), 512 threads.
// ---------------------------------------------------------------------------
__global__ __launch_bounds__(512, 1) void k_attn(
    const float* __restrict__ x_row,
    const float* __restrict__ bq, const float* __restrict__ bk,
    const float* __restrict__ bv,
    const float* __restrict__ gamma1, float* __restrict__ out) {
    extern __shared__ char smc[];
    u32 sm32 = smem_u32(smc);
    int t = threadIdx.x, wid = t >> 5, L = t & 31;

    // all three weights (192KB linear, layout final) once per block
#pragma unroll
    for (int i = 0; i < 24; i++) {
        int idx = i * 512 + t;
        cp16(sm32 + A_QH + idx * 16, g_wp + 65536 + idx * 16);
    }
    cp_commit();

    int obase = (wid & 3) * 32, sbase = (wid >> 2) * 16;
    int m = L >> 3;
    int rA_off = (m & 1) * 8 + (L & 7);
    int kbA_off = (m >> 1) * 16;
    int nrB_off = ((m >> 1) & 1) * 8 + (L & 7);
    int kbB_off = (m & 1) * 16;

    float bqv[2][2], bkv[2][2], bvv[2][2];
#pragma unroll
    for (int mf = 0; mf < 2; mf++)
#pragma unroll
        for (int hf = 0; hf < 2; hf++) {
            int o = obase + mf * 16 + (L >> 2) + hf * 8;
            bqv[mf][hf] = bq[o]; bkv[mf][hf] = bk[o]; bvv[mf][hf] = bv[o];
        }
    float gm = gamma1[0];

    bool first = true;
    for (int u = blockIdx.x; u < AUNITS; u += gridDim.x) {
        int b = u / CTIL, tile = u % CTIL;
        int s0 = tile * 64;

        // stage hn tile [64 s][128 c]: affine+relu+split, 256B pitch swizzled
        {
            int srow = t >> 3, cb = (t & 7) * 16;
            const float4* hp  = reinterpret_cast<const float4*>(
                g_h + ((size_t)b * NKS + s0 + srow) * CC + cb);
            const float4* scp = reinterpret_cast<const float4*>(g_scale + b * CC + cb);
            const float4* shp = reinterpret_cast<const float4*>(g_shift + b * CC + cb);
            u32 rowb = (u32)(srow * 256);
            u32 xm = (u32)((srow & 7) << 4);
#pragma unroll
            for (int i = 0; i < 4; i++) {
                float4 v  = hp[i];
                float4 sc = scp[i];
                float4 sh = shp[i];
                v.x = fmaxf(fmaf(v.x, sc.x, sh.x), 0.f);
                v.y = fmaxf(fmaf(v.y, sc.y, sh.y), 0.f);
                v.z = fmaxf(fmaf(v.z, sc.z, sh.z), 0.f);
                v.w = fmaxf(fmaf(v.w, sc.w, sh.w), 0.f);
                u32 h0, l0, h1, l1;
                split2(v.x, v.y, h0, l0);
                split2(v.z, v.w, h1, l1);
                u32 ad = rowb + (((u32)(cb * 2 + i * 8)) ^ xm);
                *reinterpret_cast<u64*>(smc + A_HH + ad) = ((u64)h1 << 32) | h0;
                *reinterpret_cast<u64*>(smc + A_HL + ad) = ((u64)l1 << 32) | l0;
            }
        }
        if (first) { cp_wait0(); first = false; }
        __syncthreads();

        float dq[2][2][4], dk[2][2][4], dv[2][2][4];
#pragma unroll
        for (int mf = 0; mf < 2; mf++)
#pragma unroll
            for (int nf = 0; nf < 2; nf++)
#pragma unroll
                for (int j = 0; j < 4; j++) { dq[mf][nf][j] = 0.f; dk[mf][nf][j] = 0.f; dv[mf][nf][j] = 0.f; }

#pragma unroll
        for (int ks = 0; ks < 8; ks++) {
            // B (hn) fragments: one 16-row group, shared by q,k,v
            int nrow = sbase + nrB_off;
            u32 adB = (u32)(nrow * 256) + (u32)((ks * 32 + kbB_off) ^ ((nrow & 7) << 4));
            u32 r[4];
            u32 bh[2][2], bl[2][2];
            ldsm4(r, sm32 + A_HH + adB);
            bh[0][0] = r[0]; bh[0][1] = r[1]; bh[1][0] = r[2]; bh[1][1] = r[3];
            ldsm4(r, sm32 + A_HL + adB);
            bl[0][0] = r[0]; bl[0][1] = r[1]; bl[1][0] = r[2]; bl[1][1] = r[3];

            u32 rowAd[2];
#pragma unroll
            for (int mf = 0; mf < 2; mf++) {
                int row = obase + mf * 16 + rA_off;
                rowAd[mf] = (u32)(row * 256) + (u32)((ks * 32 + kbA_off) ^ ((row & 7) << 4));
            }
            u32 ah[2][4], al[2][4];
            // Q
#pragma unroll
            for (int mf = 0; mf < 2; mf++) {
                ldsm4(ah[mf], sm32 + A_QH + rowAd[mf]);
                ldsm4(al[mf], sm32 + A_QL + rowAd[mf]);
            }
#pragma unroll
            for (int mf = 0; mf < 2; mf++)
#pragma unroll
                for (int nf = 0; nf < 2; nf++) {
                    mma16816(dq[mf][nf], ah[mf], bh[nf]);
                    mma16816(dq[mf][nf], ah[mf], bl[nf]);
                    mma16816(dq[mf][nf], al[mf], bh[nf]);
                }
            // K
#pragma unroll
            for (int mf = 0; mf < 2; mf++) {
                ldsm4(ah[mf], sm32 + A_KH + rowAd[mf]);
                ldsm4(al[mf], sm32 + A_KL + rowAd[mf]);
            }
#pragma unroll
            for (int mf = 0; mf < 2; mf++)
#pragma unroll
                for (int nf = 0; nf < 2; nf++) {
                    mma16816(dk[mf][nf], ah[mf], bh[nf]);
                    mma16816(dk[mf][nf], ah[mf], bl[nf]);
                    mma16816(dk[mf][nf], al[mf], bh[nf]);
                }
            // V
#pragma unroll
            for (int mf = 0; mf < 2; mf++) {
                ldsm4(ah[mf], sm32 + A_VH + rowAd[mf]);
                ldsm4(al[mf], sm32 + A_VL + rowAd[mf]);
            }
#pragma unroll
            for (int mf = 0; mf < 2; mf++)
#pragma unroll
                for (int nf = 0; nf < 2; nf++) {
                    mma16816(dv[mf][nf], ah[mf], bh[nf]);
                    mma16816(dv[mf][nf], ah[mf], bl[nf]);
                    mma16816(dv[mf][nf], al[mf], bh[nf]);
                }
        }

        // epilogue: softmax over this warp's 16-s group (quad shfl) + V + residual
#pragma unroll
        for (int mf = 0; mf < 2; mf++)
#pragma unroll
            for (int hf = 0; hf < 2; hf++) {
                float bq_ = bqv[mf][hf], bk_ = bkv[mf][hf], bv_ = bvv[mf][hf];
                float p0 = (dq[mf][0][hf * 2]     + bq_) * (dk[mf][0][hf * 2]     + bk_);
                float p1 = (dq[mf][0][hf * 2 + 1] + bq_) * (dk[mf][0][hf * 2 + 1] + bk_);
                float p2 = (dq[mf][1][hf * 2]     + bq_) * (dk[mf][1][hf * 2]     + bk_);
                float p3 = (dq[mf][1][hf * 2 + 1] + bq_) * (dk[mf][1][hf * 2 + 1] + bk_);
                float mx = fmaxf(fmaxf(p0, p1), fmaxf(p2, p3));
                mx = fmaxf(mx, __shfl_xor_sync(0xffffffffu, mx, 1));
                mx = fmaxf(mx, __shfl_xor_sync(0xffffffffu, mx, 2));
                float e0 = __expf(p0 - mx), e1 = __expf(p1 - mx);
                float e2 = __expf(p2 - mx), e3 = __expf(p3 - mx);
                float den = e0 + e1 + e2 + e3;
                float acc = e0 * (dv[mf][0][hf * 2]     + bv_)
                          + e1 * (dv[mf][0][hf * 2 + 1] + bv_)
                          + e2 * (dv[mf][1][hf * 2]     + bv_)
                          + e3 * (dv[mf][1][hf * 2 + 1] + bv_);
                den += __shfl_xor_sync(0xffffffffu, den, 1);
                den += __shfl_xor_sync(0xffffffffu, den, 2);
                acc += __shfl_xor_sync(0xffffffffu, acc, 1);
                acc += __shfl_xor_sync(0xffffffffu, acc, 2);
                if ((L & 3) == 0) {
                    int n = tile * 4 + (wid >> 2);
                    int o = obase + mf * 16 + (L >> 2) + hf * 8;
                    size_t oi = ((size_t)b * CC + o) * NN + n;
                    out[oi] = x_row[oi] + gm * (acc / den);
                }
            }
        __syncthreads();   // H buffers reused next unit
    }
}

// ---------------------------------------------------------------------------
extern "C" void kernel_launch(void* const* d_in, const int* in_sizes, int n_in,
                              void* d_out, int out_size) {
    const float* x_row   = (const float*)d_in[0];
    const float* x_local = (const float*)d_in[1];
    const float* w0      = (const float*)d_in[2];
    const float* b0      = (const float*)d_in[3];
    const float* bn_g    = (const float*)d_in[4];
    const float* bn_b    = (const float*)d_in[5];
    const float* wq      = (const float*)d_in[6];
    const float* bq      = (const float*)d_in[7];
    const float* wk      = (const float*)d_in[8];
    const float* bk      = (const float*)d_in[9];
    const float* wv      = (const float*)d_in[10];
    const float* bv      = (const float*)d_in[11];
    const float* gamma1  = (const float*)d_in[12];
    float* out = (float*)d_out;

    cudaFuncSetAttribute(k_conv0, cudaFuncAttributeMaxDynamicSharedMemorySize, C_SMEM);
    cudaFuncSetAttribute(k_attn,  cudaFuncAttributeMaxDynamicSharedMemorySize, A_SMEM);

    k_prep<<<4, 256>>>(w0, wq, wk, wv);
    k_conv0<<<dim3(CTIL, BB), 256, C_SMEM>>>(x_local, b0);
    k_stats<<<1, 1024>>>(bn_g, bn_b);
    k_attn<<<APER, 512, A_SMEM>>>(x_row, bq, bk, bv, gamma1, out);
}